// round 3
// baseline (speedup 1.0000x reference)
#include <cuda_runtime.h>
#include <cuda_bf16.h>

// Problem: x (16,64,64,512) f32, W_dt (2,32), dt_bias (16), A_log (16)
// Output: [mask_w (16,64,16,64,64) ; mask_h (16,64,16,64,64)] f32 concatenated.

#define N_B      16
#define N_L      64          // H == W == 64
#define N_HEADS  16
#define HEADDIM  32
#define N_ROWS   (N_B * N_L * N_HEADS)   // 16384 rows per mask

// Scratch: projected values in transposed layouts.
// alpha: (b, H, h, W) contiguous-in-W ; beta: (b, W, h, H) contiguous-in-H
__device__ float g_alpha[N_ROWS * N_L];
__device__ float g_beta [N_ROWS * N_L];

// ---------------------------------------------------------------------------
// Stage 1: projection + softplus*A, tiled so BOTH transposed scratch layouts
// get sector-coalesced float4 stores.
// Block tile: Hi in [Hi0,Hi0+16), Wi in [Wi0,Wi0+16), heads [h0,h0+4).
// Grid: 16(b) * 4(HiT) * 4(WiT) * 4(hG) = 1024 blocks, 256 threads.
// ---------------------------------------------------------------------------
__global__ void __launch_bounds__(256) pe2d_stage1(
    const float* __restrict__ x,
    const float* __restrict__ W_dt,
    const float* __restrict__ dt_bias,
    const float* __restrict__ A_log)
{
    __shared__ float w0[HEADDIM];
    __shared__ float w1[HEADDIM];
    __shared__ float s_bias[N_HEADS];
    __shared__ float s_A[N_HEADS];
    __shared__ float s_a[16][4][16];   // [Hi_l][h_l][Wi_l]  (alpha)
    __shared__ float s_b[16][4][17];   // [Wi_l][h_l][Hi_l]  (beta, padded)

    const int t = threadIdx.x;
    if (t < HEADDIM) { w0[t] = W_dt[t]; w1[t] = W_dt[HEADDIM + t]; }
    if (t < N_HEADS) { s_bias[t] = dt_bias[t]; s_A[t] = -expf(A_log[t]); }
    __syncthreads();

    const int bid = blockIdx.x;
    const int h0  = (bid & 3) * 4;
    const int Wi0 = ((bid >> 2) & 3) * 16;
    const int Hi0 = ((bid >> 4) & 3) * 16;
    const int b   = bid >> 6;

    const int h_l  = t & 3;
    const int Wi_l = (t >> 2) & 15;
    const int hib  = t >> 6;           // 0..3

    const int h    = h0 + h_l;
    const float bias = s_bias[h];
    const float Av   = s_A[h];

#pragma unroll
    for (int it = 0; it < 4; it++) {
        const int Hi_l = it * 4 + hib;
        const int bs   = b * 4096 + (Hi0 + Hi_l) * 64 + (Wi0 + Wi_l);
        const float4* xp = reinterpret_cast<const float4*>(
            x + (size_t)bs * 512 + (size_t)h * HEADDIM);

        float d0 = 0.f, d1 = 0.f;
#pragma unroll
        for (int k = 0; k < 8; k++) {
            float4 v = xp[k];
            d0 += v.x * w0[4*k+0] + v.y * w0[4*k+1] + v.z * w0[4*k+2] + v.w * w0[4*k+3];
            d1 += v.x * w1[4*k+0] + v.y * w1[4*k+1] + v.z * w1[4*k+2] + v.w * w1[4*k+3];
        }

        const float a  = d0 + bias;
        const float be = d1 + bias;
        // numerically stable softplus
        const float sa = fmaxf(a,  0.f) + log1pf(expf(-fabsf(a)));
        const float sb = fmaxf(be, 0.f) + log1pf(expf(-fabsf(be)));

        s_a[Hi_l][h_l][Wi_l] = sa * Av;
        s_b[Wi_l][h_l][Hi_l] = sb * Av;
    }
    __syncthreads();

    // ---- alpha out: ((b*64+Hi)*16+h)*64 + Wi : 16-float runs
    {
        const int Hi_l = t >> 4;
        const int hh   = (t >> 2) & 3;
        const int Wq   = (t & 3) * 4;
        const float4 v = *reinterpret_cast<const float4*>(&s_a[Hi_l][hh][Wq]);
        float* dst = g_alpha +
            (((size_t)b * N_L + (Hi0 + Hi_l)) * N_HEADS + (h0 + hh)) * N_L
            + Wi0 + Wq;
        *reinterpret_cast<float4*>(dst) = v;
    }
    // ---- beta out: ((b*64+Wi)*16+h)*64 + Hi
    {
        const int Wi_l = t >> 4;
        const int hh   = (t >> 2) & 3;
        const int Hq   = (t & 3) * 4;
        float4 v;
        v.x = s_b[Wi_l][hh][Hq + 0];
        v.y = s_b[Wi_l][hh][Hq + 1];
        v.z = s_b[Wi_l][hh][Hq + 2];
        v.w = s_b[Wi_l][hh][Hq + 3];
        float* dst = g_beta +
            (((size_t)b * N_L + (Wi0 + Wi_l)) * N_HEADS + (h0 + hh)) * N_L
            + Hi0 + Hq;
        *reinterpret_cast<float4*>(dst) = v;
    }
}

// ---------------------------------------------------------------------------
// Stage 2: warp-per-row. Each warp: load 64 vals, shfl inclusive scan,
// park prefix in smem, emit 64x64 mask with 32 float4 stores per lane.
// Block = 8 warps = 8 rows. Grid = 2*16384/8 = 4096 blocks. Zero block bars.
// ---------------------------------------------------------------------------
__global__ void __launch_bounds__(256) pe2d_stage2(
    float* __restrict__ out, long long half)
{
    __shared__ float s_cs[8][64];

    const int t    = threadIdx.x;
    const int warp = t >> 5;
    const int lane = t & 31;

    const int row_g = blockIdx.x * 8 + warp;       // 0 .. 32767
    const int r = row_g & (N_ROWS - 1);            // row within mask
    const int m = row_g >> 14;                     // 0 = mask_w, 1 = mask_h
    const float* src = m ? g_beta : g_alpha;

    // load two halves of the row
    float v0 = src[(size_t)r * N_L + lane];
    float v1 = src[(size_t)r * N_L + 32 + lane];

    // warp inclusive scan of each half
#pragma unroll
    for (int off = 1; off < 32; off <<= 1) {
        float u0 = __shfl_up_sync(0xffffffffu, v0, off);
        float u1 = __shfl_up_sync(0xffffffffu, v1, off);
        if (lane >= off) { v0 += u0; v1 += u1; }
    }
    // add total of first half to second half
    const float tot0 = __shfl_sync(0xffffffffu, v0, 31);
    v1 += tot0;

    s_cs[warp][lane]      = v0;
    s_cs[warp][lane + 32] = v1;
    __syncwarp();

    const float* cs = s_cs[warp];
    float4* op = reinterpret_cast<float4*>(
        out + (size_t)m * (size_t)half + (size_t)r * (N_L * N_L));

    // 1024 float4 quads per row; lane handles e = lane + 32k
#pragma unroll
    for (int k = 0; k < 32; k++) {
        const int e  = lane + k * 32;
        const int i  = e >> 4;            // row   0..63
        const int j0 = (e & 15) << 2;     // col quad base
        const float ci = cs[i];
        const float s0 = ci - cs[j0 + 0];
        const float s1 = ci - cs[j0 + 1];
        const float s2 = ci - cs[j0 + 2];
        const float s3 = ci - cs[j0 + 3];
        float4 v;
        v.x = (i >= j0 + 0) ? s0 : -s0;
        v.y = (i >= j0 + 1) ? s1 : -s1;
        v.z = (i >= j0 + 2) ? s2 : -s2;
        v.w = (i >= j0 + 3) ? s3 : -s3;
        op[e] = v;
    }
}

// ---------------------------------------------------------------------------
extern "C" void kernel_launch(void* const* d_in, const int* in_sizes, int n_in,
                              void* d_out, int out_size)
{
    const float* x       = (const float*)d_in[0];
    const float* W_dt    = (const float*)d_in[1];
    const float* dt_bias = (const float*)d_in[2];
    const float* A_log   = (const float*)d_in[3];
    float* out = (float*)d_out;

    // Stage 1: 1024 blocks x 256 threads, tiled transposed scratch writes
    pe2d_stage1<<<1024, 256>>>(x, W_dt, dt_bias, A_log);

    // Stage 2: 4096 blocks x 256 threads (warp per row)
    long long half = (long long)out_size / 2;
    pe2d_stage2<<<(2 * N_ROWS) / 8, 256>>>(out, half);
}

// round 6
// speedup vs baseline: 1.2437x; 1.2437x over previous
#include <cuda_runtime.h>
#include <cuda_bf16.h>

// Problem: x (16,64,64,512) f32, W_dt (2,32), dt_bias (16), A_log (16)
// Output: [mask_w (16,64,16,64,64) ; mask_h (16,64,16,64,64)] f32 concatenated.

#define N_B      16
#define N_L      64          // H == W == 64
#define N_HEADS  16
#define HEADDIM  32
#define N_ROWS   (N_B * N_L * N_HEADS)   // 16384 rows per mask
#define XPAD     36          // padded words per 32-float (bs,h) chunk

// Scratch: projected values in transposed layouts.
// alpha: (b, H, h, W) contiguous-in-W ; beta: (b, W, h, H) contiguous-in-H
__device__ float g_alpha[N_ROWS * N_L];
__device__ float g_beta [N_ROWS * N_L];

// ---------------------------------------------------------------------------
// Stage 1: projection + softplus*A.
// x staged through shared memory with fully coalesced LDG.128 (nL=4/instr;
// the direct per-thread version was L1tex wavefront-bound: nL=32/instr,
// 8.39M wavefronts -> ~31us serialization). Dot products read smem
// (36-word padded chunks: conflict-free LDS.128/STS.128 in every 8-lane phase).
// Block tile: 16 Hi x 16 Wi x 4 heads; 4 iterations of 4 Hi each.
// Grid: 16(b) * 4(HiT) * 4(WiT) * 4(hG) = 1024 blocks, 256 threads.
// ---------------------------------------------------------------------------
__global__ void __launch_bounds__(256) pe2d_stage1(
    const float* __restrict__ x,
    const float* __restrict__ W_dt,
    const float* __restrict__ dt_bias,
    const float* __restrict__ A_log)
{
    __shared__ float w0[HEADDIM];
    __shared__ float w1[HEADDIM];
    __shared__ float s_x[64 * 4 * XPAD];   // 64 bs_local x 4 heads x 36 words
    __shared__ float s_a[16][4][16];       // [Hi_l][h_l][Wi_l]  (alpha)
    __shared__ float s_b[16][4][17];       // [Wi_l][h_l][Hi_l]  (beta, padded)

    const int t = threadIdx.x;
    if (t < HEADDIM) { w0[t] = W_dt[t]; w1[t] = W_dt[HEADDIM + t]; }

    const int bid = blockIdx.x;
    const int h0  = (bid & 3) * 4;
    const int Wi0 = ((bid >> 2) & 3) * 16;
    const int Hi0 = ((bid >> 4) & 3) * 16;
    const int b   = bid >> 6;

    const int h_l  = t & 3;
    const int Wi_l = (t >> 2) & 15;
    const int hib  = t >> 6;           // 0..3

    const float bias = dt_bias[h0 + h_l];        // tiny, L1-resident
    const float Av   = -expf(A_log[h0 + h_l]);

#pragma unroll
    for (int it = 0; it < 4; it++) {
        // ---- coalesced load phase: 64 bs-chunks x 512 B -> smem ----
#pragma unroll
        for (int j = 0; j < 8; j++) {
            const int q      = j * 256 + t;       // 0..2047 (float4 index)
            const int bs_loc = q >> 5;            // 0..63
            const int p      = q & 31;            // piece within 512 B
            const int hi4    = bs_loc >> 4;       // 0..3
            const int wi     = bs_loc & 15;       // 0..15
            const int gbs    = b * 4096 + (Hi0 + it * 4 + hi4) * 64 + (Wi0 + wi);
            const float4 v = __ldcs(reinterpret_cast<const float4*>(
                x + (size_t)gbs * 512 + h0 * HEADDIM) + p);
            *reinterpret_cast<float4*>(
                &s_x[(bs_loc * 4 + (p >> 3)) * XPAD + (p & 7) * 4]) = v;
        }
        __syncthreads();   // (also orders w0/w1 writes before first compute)

        // ---- compute phase: one dot pair per thread from smem ----
        const float* base = &s_x[((hib * 16 + Wi_l) * 4 + h_l) * XPAD];
        float d0 = 0.f, d1 = 0.f;
#pragma unroll
        for (int k = 0; k < 8; k++) {
            const float4 v = *reinterpret_cast<const float4*>(&base[k * 4]);
            d0 = fmaf(v.x, w0[4*k+0], fmaf(v.y, w0[4*k+1],
                 fmaf(v.z, w0[4*k+2], fmaf(v.w, w0[4*k+3], d0))));
            d1 = fmaf(v.x, w1[4*k+0], fmaf(v.y, w1[4*k+1],
                 fmaf(v.z, w1[4*k+2], fmaf(v.w, w1[4*k+3], d1))));
        }

        const float a  = d0 + bias;
        const float be = d1 + bias;
        // numerically stable softplus
        const float sa = fmaxf(a,  0.f) + log1pf(expf(-fabsf(a)));
        const float sb = fmaxf(be, 0.f) + log1pf(expf(-fabsf(be)));

        const int Hi_l = it * 4 + hib;
        s_a[Hi_l][h_l][Wi_l] = sa * Av;
        s_b[Wi_l][h_l][Hi_l] = sb * Av;
        __syncthreads();   // protects s_x for next iteration
    }

    // ---- alpha out: ((b*64+Hi)*16+h)*64 + Wi : coalesced float4 ----
    {
        const int Hi_l = t >> 4;
        const int hh   = (t >> 2) & 3;
        const int Wq   = (t & 3) * 4;
        const float4 v = *reinterpret_cast<const float4*>(&s_a[Hi_l][hh][Wq]);
        float* dst = g_alpha +
            (((size_t)b * N_L + (Hi0 + Hi_l)) * N_HEADS + (h0 + hh)) * N_L
            + Wi0 + Wq;
        *reinterpret_cast<float4*>(dst) = v;
    }
    // ---- beta out: ((b*64+Wi)*16+h)*64 + Hi ----
    {
        const int Wi_l = t >> 4;
        const int hh   = (t >> 2) & 3;
        const int Hq   = (t & 3) * 4;
        float4 v;
        v.x = s_b[Wi_l][hh][Hq + 0];
        v.y = s_b[Wi_l][hh][Hq + 1];
        v.z = s_b[Wi_l][hh][Hq + 2];
        v.w = s_b[Wi_l][hh][Hq + 3];
        float* dst = g_beta +
            (((size_t)b * N_L + (Wi0 + Wi_l)) * N_HEADS + (h0 + hh)) * N_L
            + Hi0 + Hq;
        *reinterpret_cast<float4*>(dst) = v;
    }
}

// ---------------------------------------------------------------------------
// Stage 2: warp-per-row. Shfl inclusive scan (no block barriers), prefix in
// smem, 32 streaming float4 stores per lane.
// Block = 8 warps = 8 rows. Grid = 2*16384/8 = 4096 blocks.
// Measured R3: 82.8us @ 6.58 TB/s effective -> at the LTS chip cap; done.
// ---------------------------------------------------------------------------
__global__ void __launch_bounds__(256) pe2d_stage2(
    float* __restrict__ out, long long half)
{
    __shared__ float s_cs[8][64];

    const int t    = threadIdx.x;
    const int warp = t >> 5;
    const int lane = t & 31;

    const int row_g = blockIdx.x * 8 + warp;       // 0 .. 32767
    const int r = row_g & (N_ROWS - 1);            // row within mask
    const int m = row_g >> 14;                     // 0 = mask_w, 1 = mask_h
    const float* src = m ? g_beta : g_alpha;

    float v0 = src[(size_t)r * N_L + lane];
    float v1 = src[(size_t)r * N_L + 32 + lane];

#pragma unroll
    for (int off = 1; off < 32; off <<= 1) {
        float u0 = __shfl_up_sync(0xffffffffu, v0, off);
        float u1 = __shfl_up_sync(0xffffffffu, v1, off);
        if (lane >= off) { v0 += u0; v1 += u1; }
    }
    const float tot0 = __shfl_sync(0xffffffffu, v0, 31);
    v1 += tot0;

    s_cs[warp][lane]      = v0;
    s_cs[warp][lane + 32] = v1;
    __syncwarp();

    const float* cs = s_cs[warp];
    float4* op = reinterpret_cast<float4*>(
        out + (size_t)m * (size_t)half + (size_t)r * (N_L * N_L));

#pragma unroll
    for (int k = 0; k < 32; k++) {
        const int e  = lane + k * 32;
        const int i  = e >> 4;            // row   0..63
        const int j0 = (e & 15) << 2;     // col quad base
        const float ci = cs[i];
        const float s0 = ci - cs[j0 + 0];
        const float s1 = ci - cs[j0 + 1];
        const float s2 = ci - cs[j0 + 2];
        const float s3 = ci - cs[j0 + 3];
        float4 v;
        v.x = (i >= j0 + 0) ? s0 : -s0;
        v.y = (i >= j0 + 1) ? s1 : -s1;
        v.z = (i >= j0 + 2) ? s2 : -s2;
        v.w = (i >= j0 + 3) ? s3 : -s3;
        __stcs(&op[e], v);                // streaming store, evict-first
    }
}

// ---------------------------------------------------------------------------
extern "C" void kernel_launch(void* const* d_in, const int* in_sizes, int n_in,
                              void* d_out, int out_size)
{
    const float* x       = (const float*)d_in[0];
    const float* W_dt    = (const float*)d_in[1];
    const float* dt_bias = (const float*)d_in[2];
    const float* A_log   = (const float*)d_in[3];
    float* out = (float*)d_out;

    pe2d_stage1<<<1024, 256>>>(x, W_dt, dt_bias, A_log);

    long long half = (long long)out_size / 2;
    pe2d_stage2<<<(2 * N_ROWS) / 8, 256>>>(out, half);
}